// round 3
// baseline (speedup 1.0000x reference)
#include <cuda_runtime.h>
#include <math.h>
#include <stdint.h>

#define TT 512
#define BB 64
#define HH 1024
#define NCTA 128
#define NTHR 256

typedef unsigned long long u64;

__device__ float g_pre[(size_t)TT * HH * BB];   // [t][h][b]
__device__ float g_h0[2][HH * BB];              // [k][b], H0[t] in g_h0[t&1]
__device__ float g_h1[2][HH * BB];              // H1[t] in g_h1[t&1]
__device__ u64 g_arrive;
__device__ volatile u64 g_release;

// Grid-wide ticket barrier (monotonic across graph replays; 1 CTA/SM resident)
__device__ __forceinline__ void gsync()
{
    __syncthreads();
    if (threadIdx.x == 0) {
        __threadfence();
        u64 old = atomicAdd(&g_arrive, 1ULL);
        u64 tgt = old / NCTA + 1ULL;
        if ((old % NCTA) == (NCTA - 1)) { __threadfence(); g_release = tgt; }
        else { while (g_release < tgt) {} }
        __threadfence();
    }
    __syncthreads();
}

__device__ __forceinline__ void ffma2(u64& d, u64 a, u64 b)
{
    asm("fma.rn.f32x2 %0,%1,%2,%0;" : "+l"(d) : "l"(a), "l"(b));
}
__device__ __forceinline__ void fadd2(u64& d, u64 a)
{
    asm("add.rn.f32x2 %0,%0,%1;" : "+l"(d) : "l"(a));
}

// ---------------------------------------------------------------------------
// pregemm: g_pre[t][j][b] = x[t][b]·Wih0[j] + bih0[j] + bhh0[j]  (unchanged R1)
// ---------------------------------------------------------------------------
__global__ void __launch_bounds__(256) pregemm(const float* __restrict__ X,
                                               const float* __restrict__ W,
                                               const float* __restrict__ bih,
                                               const float* __restrict__ bhh)
{
    __shared__ float As[16][132];
    __shared__ float Bs[16][68];
    const int tid = threadIdx.x;
    const int m0 = blockIdx.y * 128;
    const int n0 = blockIdx.x * 64;
    const int tx = tid & 15;
    const int ty = tid >> 4;

    float acc[8][4];
#pragma unroll
    for (int i = 0; i < 8; i++)
#pragma unroll
        for (int j = 0; j < 4; j++) acc[i][j] = 0.f;

    for (int k0 = 0; k0 < 1024; k0 += 16) {
#pragma unroll
        for (int i = 0; i < 2; i++) {
            int q = tid + i * 256;
            int m = q >> 2, kq = (q & 3) << 2;
            float4 v = __ldg((const float4*)&X[(size_t)(m0 + m) * 1024 + k0 + kq]);
            As[kq + 0][m] = v.x; As[kq + 1][m] = v.y;
            As[kq + 2][m] = v.z; As[kq + 3][m] = v.w;
        }
        {
            int n = tid >> 2, kq = (tid & 3) << 2;
            float4 v = __ldg((const float4*)&W[(size_t)(n0 + n) * 1024 + k0 + kq]);
            Bs[kq + 0][n] = v.x; Bs[kq + 1][n] = v.y;
            Bs[kq + 2][n] = v.z; Bs[kq + 3][n] = v.w;
        }
        __syncthreads();
#pragma unroll
        for (int kk = 0; kk < 16; kk++) {
            float a[8], b[4];
            *(float4*)&a[0] = *(const float4*)&As[kk][ty * 8];
            *(float4*)&a[4] = *(const float4*)&As[kk][ty * 8 + 4];
            *(float4*)&b[0] = *(const float4*)&Bs[kk][tx * 4];
#pragma unroll
            for (int i = 0; i < 8; i++)
#pragma unroll
                for (int j = 0; j < 4; j++) acc[i][j] = fmaf(a[i], b[j], acc[i][j]);
        }
        __syncthreads();
    }
#pragma unroll
    for (int i = 0; i < 8; i++) {
        int gm = m0 + ty * 8 + i, t = gm >> 6, b = gm & 63;
#pragma unroll
        for (int j = 0; j < 4; j++) {
            int gn = n0 + tx * 4 + j;
            g_pre[((size_t)t * 1024 + gn) * 64 + b] = acc[i][j] + __ldg(&bih[gn]) + __ldg(&bhh[gn]);
        }
    }
}

// init: H0[-1], H1[-1] into parity buffer 1
__global__ void init_h(const float* __restrict__ h0in)
{
    int e = blockIdx.x * blockDim.x + threadIdx.x;
    if (e < 2 * BB * HH) {
        int l = e >> 16, r = e & 65535, b = r >> 10, k = r & 1023;
        float* dst = l ? g_h1[1] : g_h0[1];
        dst[k * 64 + b] = h0in[e];
    }
}

// ---------------------------------------------------------------------------
// pass: stream src[1024][64] through smem staging in 8 chunks; accumulate
// NW weight matrices (duplicated layout [k][16]) into f32x2 acc tiles.
// Thread tile: 2 j x 8 b (4 b-pairs). Split-K by warp g (128 k each).
// ---------------------------------------------------------------------------
template<int NW>
__device__ __forceinline__ void pass(const float* __restrict__ src,
                                     const float* __restrict__ wdA,
                                     const float* __restrict__ wdB,
                                     float* hs,
                                     u64 (&aA)[2][4], u64 (&aB)[2][4],
                                     int b0, int j0, int g)
{
    const float4* s4 = (const float4*)src;
    float4 pf[8];
#pragma unroll
    for (int i = 0; i < 8; i++) pf[i] = __ldcg(s4 + threadIdx.x + i * 256);

    for (int c = 0; c < 8; c++) {
        __syncthreads();
#pragma unroll
        for (int i = 0; i < 8; i++) ((float4*)hs)[threadIdx.x + i * 256] = pf[i];
        __syncthreads();
        if (c < 7) {
            const float4* n4 = s4 + (size_t)(c + 1) * 2048;
#pragma unroll
            for (int i = 0; i < 8; i++) pf[i] = __ldcg(n4 + threadIdx.x + i * 256);
        }
#pragma unroll
        for (int kk = 0; kk < 16; kk++) {
            int kl = g * 16 + kk;
            int kg = c * 128 + kl;
            ulonglong2 h0 = *(const ulonglong2*)(hs + kl * 64 + b0);
            ulonglong2 h1 = *(const ulonglong2*)(hs + kl * 64 + b0 + 4);
            ulonglong2 wa = *(const ulonglong2*)(wdA + (size_t)kg * 16 + j0 * 2);
            ffma2(aA[0][0], wa.x, h0.x); ffma2(aA[0][1], wa.x, h0.y);
            ffma2(aA[0][2], wa.x, h1.x); ffma2(aA[0][3], wa.x, h1.y);
            ffma2(aA[1][0], wa.y, h0.x); ffma2(aA[1][1], wa.y, h0.y);
            ffma2(aA[1][2], wa.y, h1.x); ffma2(aA[1][3], wa.y, h1.y);
            if (NW == 2) {
                ulonglong2 wb = *(const ulonglong2*)(wdB + (size_t)kg * 16 + j0 * 2);
                ffma2(aB[0][0], wb.x, h0.x); ffma2(aB[0][1], wb.x, h0.y);
                ffma2(aB[0][2], wb.x, h1.x); ffma2(aB[0][3], wb.x, h1.y);
                ffma2(aB[1][0], wb.y, h0.x); ffma2(aB[1][1], wb.y, h0.y);
                ffma2(aB[1][2], wb.y, h1.x); ffma2(aB[1][3], wb.y, h1.y);
            }
        }
    }
}

__device__ __forceinline__ void stred(float* red, u64 (&a)[2][4], int g, int b0, int j0)
{
#pragma unroll
    for (int j = 0; j < 2; j++)
#pragma unroll
        for (int p = 0; p < 4; p++)
            *(u64*)&red[(g * 8 + j0 + j) * 66 + b0 + 2 * p] = a[j][p];
}

// ---------------------------------------------------------------------------
// Persistent loop: 1 barrier/step. Interval t computes H1[t] and H0[t+1].
// CTA owns j in [8*bid, 8*bid+8). SMEM: 3 duplicated weight slices (64KB ea),
// 32KB staging (aliased as reduction buffer), bias.
// ---------------------------------------------------------------------------
__global__ void __launch_bounds__(NTHR, 1) rnn_persist(
    const float* __restrict__ Whh0, const float* __restrict__ Wih1,
    const float* __restrict__ Whh1, const float* __restrict__ bih1,
    const float* __restrict__ bhh1, float* __restrict__ out)
{
    extern __shared__ float sm[];
    float* wd0 = sm;            // Whh0 dup [k][16]
    float* wd1 = sm + 16384;    // Wih1 dup
    float* wd2 = sm + 32768;    // Whh1 dup
    float* hs  = sm + 49152;    // 8192 staging / red alias
    float* bias1 = sm + 57344;  // 8

    const int tid = threadIdx.x, lane = tid & 31, g = tid >> 5;
    const int b0 = (lane & 7) * 8;
    const int j0 = (lane >> 3) * 2;
    const int jbase = blockIdx.x * 8;

    for (int idx = tid; idx < 8192; idx += NTHR) {
        int jj = idx >> 10, k = idx & 1023;
        float w0 = __ldg(&Whh0[(size_t)(jbase + jj) * 1024 + k]);
        float w1 = __ldg(&Wih1[(size_t)(jbase + jj) * 1024 + k]);
        float w2 = __ldg(&Whh1[(size_t)(jbase + jj) * 1024 + k]);
        wd0[k * 16 + 2 * jj] = w0; wd0[k * 16 + 2 * jj + 1] = w0;
        wd1[k * 16 + 2 * jj] = w1; wd1[k * 16 + 2 * jj + 1] = w1;
        wd2[k * 16 + 2 * jj] = w2; wd2[k * 16 + 2 * jj + 1] = w2;
    }
    if (tid < 8) bias1[tid] = __ldg(&bih1[jbase + tid]) + __ldg(&bhh1[jbase + tid]);

    u64 aA[2][4], aB[2][4], aC[2][4], aD[2][4];

    // Prologue: H0[0] = tanh(pre[0] + H0[-1]@Whh0^T)
#pragma unroll
    for (int j = 0; j < 2; j++)
#pragma unroll
        for (int p = 0; p < 4; p++) aA[j][p] = 0ULL;
    pass<1>(g_h0[1], wd0, wd0, hs, aA, aD, b0, j0, g);
    __syncthreads();
    stred(hs, aA, g, b0, j0);
    __syncthreads();
#pragma unroll
    for (int e2 = 0; e2 < 2; e2++) {
        int e = tid + e2 * NTHR, j = e >> 6, b = e & 63;
        float s = 0.f;
#pragma unroll
        for (int gg = 0; gg < 8; gg++) s += hs[(gg * 8 + j) * 66 + b];
        int jg = jbase + j;
        float v = s + __ldcg(&g_pre[(size_t)jg * 64 + b]);
        __stcg(&g_h0[0][jg * 64 + b], tanhf(v));
    }
    gsync();

    for (int t = 0; t < TT; t++) {
        const int p = t & 1;
#pragma unroll
        for (int j = 0; j < 2; j++)
#pragma unroll
            for (int q = 0; q < 4; q++) { aA[j][q] = 0ULL; aB[j][q] = 0ULL; aC[j][q] = 0ULL; }

        // H0[t] feeds both Wih1 (->aA) and Whh0-next (->aB); H1[t-1] feeds Whh1 (->aC)
        pass<2>(g_h0[p], wd1, wd0, hs, aA, aB, b0, j0, g);
        pass<1>(g_h1[p ^ 1], wd2, wd2, hs, aC, aD, b0, j0, g);

        // combine h1 partials
#pragma unroll
        for (int j = 0; j < 2; j++)
#pragma unroll
            for (int q = 0; q < 4; q++) fadd2(aA[j][q], aC[j][q]);

        __syncthreads();
        stred(hs, aA, g, b0, j0);
        __syncthreads();
#pragma unroll
        for (int e2 = 0; e2 < 2; e2++) {
            int e = tid + e2 * NTHR, j = e >> 6, b = e & 63;
            float s = 0.f;
#pragma unroll
            for (int gg = 0; gg < 8; gg++) s += hs[(gg * 8 + j) * 66 + b];
            int jg = jbase + j;
            float h = tanhf(s + bias1[j]);
            __stcg(&g_h1[p][jg * 64 + b], h);
            out[((size_t)t * 64 + b) * 1024 + jg] = h;
        }

        if (t < TT - 1) {
            __syncthreads();
            stred(hs, aB, g, b0, j0);
            __syncthreads();
#pragma unroll
            for (int e2 = 0; e2 < 2; e2++) {
                int e = tid + e2 * NTHR, j = e >> 6, b = e & 63;
                float s = 0.f;
#pragma unroll
                for (int gg = 0; gg < 8; gg++) s += hs[(gg * 8 + j) * 66 + b];
                int jg = jbase + j;
                float v = s + __ldcg(&g_pre[((size_t)(t + 1) * 1024 + jg) * 64 + b]);
                __stcg(&g_h0[p ^ 1][jg * 64 + b], tanhf(v));
            }
        }
        gsync();
    }

    // h_n: H0[511] in g_h0[1], H1[511] in g_h1[1]
    for (int e = blockIdx.x * NTHR + tid; e < 2 * BB * HH; e += NCTA * NTHR) {
        int l = e >> 16, r = e & 65535, b = r >> 10, k = r & 1023;
        const float* src = l ? g_h1[1] : g_h0[1];
        out[(size_t)TT * BB * HH + e] = __ldcg(&src[k * 64 + b]);
    }
}

// ---------------------------------------------------------------------------
extern "C" void kernel_launch(void* const* d_in, const int* in_sizes, int n_in,
                              void* d_out, int out_size)
{
    const float* input = (const float*)d_in[0];
    const float* h0in  = (const float*)d_in[1];
    const float* Wih0  = (const float*)d_in[2];
    const float* bih0  = (const float*)d_in[3];
    const float* Whh0  = (const float*)d_in[4];
    const float* bhh0  = (const float*)d_in[5];
    const float* Wih1  = (const float*)d_in[6];
    const float* bih1  = (const float*)d_in[7];
    const float* Whh1  = (const float*)d_in[8];
    const float* bhh1  = (const float*)d_in[9];
    float* out = (float*)d_out;

    const int smem_bytes = (57344 + 16) * 4;  // 229,440 B
    cudaFuncSetAttribute(rnn_persist, cudaFuncAttributeMaxDynamicSharedMemorySize, smem_bytes);

    pregemm<<<dim3(16, 256), 256>>>(input, Wih0, bih0, bhh0);
    init_h<<<512, 256>>>(h0in);
    rnn_persist<<<NCTA, NTHR, smem_bytes>>>(Whh0, Wih1, Whh1, bih1, bhh1, out);
}

// round 5
// speedup vs baseline: 1.8000x; 1.8000x over previous
#include <cuda_runtime.h>
#include <math.h>
#include <stdint.h>

#define TT 512
#define BB 64
#define HH 1024
#define NCTA 128
#define NTHR 256
#define CK 256   // k-values per staged chunk (64KB)

typedef unsigned long long u64;

__device__ __align__(256) float g_pre[(size_t)TT * HH * BB];  // [t][j][b]
__device__ __align__(256) float g_h0[2][HH * BB];             // [k][b]; H0[t] in g_h0[t&1]
__device__ __align__(256) float g_h1[2][HH * BB];             // H1[t] in g_h1[t&1]
__device__ u64 g_arrive;
__device__ volatile u64 g_release;

// Grid-wide ticket barrier (monotonic across graph replays; 1 CTA/SM resident)
__device__ __forceinline__ void gsync()
{
    __syncthreads();
    if (threadIdx.x == 0) {
        __threadfence();
        u64 old = atomicAdd(&g_arrive, 1ULL);
        u64 tgt = old / NCTA + 1ULL;
        if ((old % NCTA) == (NCTA - 1)) { __threadfence(); g_release = tgt; }
        else { while (g_release < tgt) {} }
        __threadfence();
    }
    __syncthreads();
}

__device__ __forceinline__ void ffma2(u64& d, u64 a, u64 b)
{ asm("fma.rn.f32x2 %0,%1,%2,%0;" : "+l"(d) : "l"(a), "l"(b)); }
__device__ __forceinline__ void fadd2(u64& d, u64 a)
{ asm("add.rn.f32x2 %0,%0,%1;" : "+l"(d) : "l"(a)); }
__device__ __forceinline__ u64 dup2(float x)
{ u64 r; asm("mov.b64 %0,{%1,%1};" : "=l"(r) : "f"(x)); return r; }
__device__ __forceinline__ void unpack2(u64 s, float& lo, float& hi)
{ asm("mov.b64 {%0,%1},%2;" : "=f"(lo), "=f"(hi) : "l"(s)); }

// cp.async one 64KB chunk (CK k x 64 b floats), L2 path (.cg) for coherence.
__device__ __forceinline__ void cp_chunk(float* sbuf, const float* gsrc)
{
    uint32_t s = (uint32_t)__cvta_generic_to_shared(sbuf) + threadIdx.x * 16;
    const char* g = (const char*)gsrc + threadIdx.x * 16;
#pragma unroll
    for (int i = 0; i < 16; i++)
        asm volatile("cp.async.cg.shared.global [%0],[%1],16;" :: "r"(s + i * 4096), "l"(g + i * 4096));
    asm volatile("cp.async.commit_group;");
}
__device__ __forceinline__ void cp_wait_all()
{ asm volatile("cp.async.wait_group 0;" ::: "memory"); }

// ---------------------------------------------------------------------------
// pregemm: g_pre[t][j][b] = x[t][b]·Wih0[j] + bih0[j] + bhh0[j]   (unchanged)
// ---------------------------------------------------------------------------
__global__ void __launch_bounds__(256) pregemm(const float* __restrict__ X,
                                               const float* __restrict__ W,
                                               const float* __restrict__ bih,
                                               const float* __restrict__ bhh)
{
    __shared__ float As[16][132];
    __shared__ float Bs[16][68];
    const int tid = threadIdx.x;
    const int m0 = blockIdx.y * 128;
    const int n0 = blockIdx.x * 64;
    const int tx = tid & 15;
    const int ty = tid >> 4;

    float acc[8][4];
#pragma unroll
    for (int i = 0; i < 8; i++)
#pragma unroll
        for (int j = 0; j < 4; j++) acc[i][j] = 0.f;

    for (int k0 = 0; k0 < 1024; k0 += 16) {
#pragma unroll
        for (int i = 0; i < 2; i++) {
            int q = tid + i * 256;
            int m = q >> 2, kq = (q & 3) << 2;
            float4 v = __ldg((const float4*)&X[(size_t)(m0 + m) * 1024 + k0 + kq]);
            As[kq + 0][m] = v.x; As[kq + 1][m] = v.y;
            As[kq + 2][m] = v.z; As[kq + 3][m] = v.w;
        }
        {
            int n = tid >> 2, kq = (tid & 3) << 2;
            float4 v = __ldg((const float4*)&W[(size_t)(n0 + n) * 1024 + k0 + kq]);
            Bs[kq + 0][n] = v.x; Bs[kq + 1][n] = v.y;
            Bs[kq + 2][n] = v.z; Bs[kq + 3][n] = v.w;
        }
        __syncthreads();
#pragma unroll
        for (int kk = 0; kk < 16; kk++) {
            float a[8], b[4];
            *(float4*)&a[0] = *(const float4*)&As[kk][ty * 8];
            *(float4*)&a[4] = *(const float4*)&As[kk][ty * 8 + 4];
            *(float4*)&b[0] = *(const float4*)&Bs[kk][tx * 4];
#pragma unroll
            for (int i = 0; i < 8; i++)
#pragma unroll
                for (int j = 0; j < 4; j++) acc[i][j] = fmaf(a[i], b[j], acc[i][j]);
        }
        __syncthreads();
    }
#pragma unroll
    for (int i = 0; i < 8; i++) {
        int gm = m0 + ty * 8 + i, t = gm >> 6, b = gm & 63;
#pragma unroll
        for (int j = 0; j < 4; j++) {
            int gn = n0 + tx * 4 + j;
            g_pre[((size_t)t * 1024 + gn) * 64 + b] = acc[i][j] + __ldg(&bih[gn]) + __ldg(&bhh[gn]);
        }
    }
}

// ---------------------------------------------------------------------------
// compute_chunk: lane owns all 8 j (4 j-pairs) x 4 b, one k per inner iter.
// wA/wB must already point at this chunk's weight rows ([CK][8] region).
// ---------------------------------------------------------------------------
template<int NW>
__device__ __forceinline__ void compute_chunk(const float* __restrict__ buf,
                                              const float* __restrict__ wA,
                                              const float* __restrict__ wB,
                                              u64 (&aA)[4][4], u64 (&aB)[4][4],
                                              int kb, int b0)
{
#pragma unroll 8
    for (int i = 0; i < 16; i++) {
        int kl = kb + 2 * i;
        float4 h4 = *(const float4*)(buf + kl * 64 + b0);
        u64 hd0 = dup2(h4.x), hd1 = dup2(h4.y), hd2 = dup2(h4.z), hd3 = dup2(h4.w);
        ulonglong2 wa0 = *(const ulonglong2*)(wA + (size_t)kl * 8);
        ulonglong2 wa1 = *(const ulonglong2*)(wA + (size_t)kl * 8 + 4);
        ffma2(aA[0][0], wa0.x, hd0); ffma2(aA[0][1], wa0.x, hd1);
        ffma2(aA[0][2], wa0.x, hd2); ffma2(aA[0][3], wa0.x, hd3);
        ffma2(aA[1][0], wa0.y, hd0); ffma2(aA[1][1], wa0.y, hd1);
        ffma2(aA[1][2], wa0.y, hd2); ffma2(aA[1][3], wa0.y, hd3);
        ffma2(aA[2][0], wa1.x, hd0); ffma2(aA[2][1], wa1.x, hd1);
        ffma2(aA[2][2], wa1.x, hd2); ffma2(aA[2][3], wa1.x, hd3);
        ffma2(aA[3][0], wa1.y, hd0); ffma2(aA[3][1], wa1.y, hd1);
        ffma2(aA[3][2], wa1.y, hd2); ffma2(aA[3][3], wa1.y, hd3);
        if (NW == 2) {
            ulonglong2 wb0 = *(const ulonglong2*)(wB + (size_t)kl * 8);
            ulonglong2 wb1 = *(const ulonglong2*)(wB + (size_t)kl * 8 + 4);
            ffma2(aB[0][0], wb0.x, hd0); ffma2(aB[0][1], wb0.x, hd1);
            ffma2(aB[0][2], wb0.x, hd2); ffma2(aB[0][3], wb0.x, hd3);
            ffma2(aB[1][0], wb0.y, hd0); ffma2(aB[1][1], wb0.y, hd1);
            ffma2(aB[1][2], wb0.y, hd2); ffma2(aB[1][3], wb0.y, hd3);
            ffma2(aB[2][0], wb1.x, hd0); ffma2(aB[2][1], wb1.x, hd1);
            ffma2(aB[2][2], wb1.x, hd2); ffma2(aB[2][3], wb1.x, hd3);
            ffma2(aB[3][0], wb1.y, hd0); ffma2(aB[3][1], wb1.y, hd1);
            ffma2(aB[3][2], wb1.y, hd2); ffma2(aB[3][3], wb1.y, hd3);
        }
    }
}

__device__ __forceinline__ void stred(u64* r64, u64 (&a)[4][4], int gr, int b0)
{
#pragma unroll
    for (int jp = 0; jp < 4; jp++) {
        ulonglong2 v0; v0.x = a[jp][0]; v0.y = a[jp][1];
        ulonglong2 v1; v1.x = a[jp][2]; v1.y = a[jp][3];
        *(ulonglong2*)&r64[(gr * 4 + jp) * 64 + b0] = v0;
        *(ulonglong2*)&r64[(gr * 4 + jp) * 64 + b0 + 2] = v1;
    }
}

// Sum 16 k-granules for (jp, b): returns u64 = (sum_j_even, sum_j_odd)
__device__ __forceinline__ u64 gather16(const u64* r64, int jp, int b)
{
    u64 s0 = r64[(0 * 4 + jp) * 64 + b];
    u64 s1 = r64[(1 * 4 + jp) * 64 + b];
#pragma unroll
    for (int gr = 2; gr < 16; gr += 2) {
        fadd2(s0, r64[(gr * 4 + jp) * 64 + b]);
        fadd2(s1, r64[((gr + 1) * 4 + jp) * 64 + b]);
    }
    fadd2(s0, s1);
    return s0;
}

// ---------------------------------------------------------------------------
// Persistent loop. 128 CTAs x 256 thr; CTA owns j [8*bid, 8*bid+8).
// SMEM floats: wt1[0,8192) Wih1 | wt0[8192,16384) Whh0 | wt2[16384,24576) Whh1
//              buf0[24576,40960) | buf1[40960,57344) | bias1[57344,+8)
// red (u64[16][4][64], 32KB) aliases buf0.
// ---------------------------------------------------------------------------
__global__ void __launch_bounds__(NTHR, 1) rnn_persist(
    const float* __restrict__ h0in,
    const float* __restrict__ Whh0, const float* __restrict__ Wih1,
    const float* __restrict__ Whh1, const float* __restrict__ bih1,
    const float* __restrict__ bhh1, float* __restrict__ out)
{
    extern __shared__ float sm[];
    float* wt1 = sm;
    float* wt0 = sm + 8192;
    float* wt2 = sm + 16384;
    float* buf0 = sm + 24576;
    float* buf1 = sm + 40960;
    float* bias1 = sm + 57344;
    u64* r64 = (u64*)buf0;

    const int tid = threadIdx.x;
    const int lane = tid & 31;
    const int g = tid >> 5;
    const int k2 = lane >> 4;            // 0/1
    const int b0 = (lane & 15) * 4;      // 16 b-groups x 4 b
    const int kb = g * 32 + k2;          // chunk-local k base (stride 2)
    const int gr = g * 2 + k2;           // reduction granule 0..15
    const int jbase = blockIdx.x * 8;
    const int ejp = tid & 3, eb = tid >> 2;  // epilogue mapping

    // --- prologue: weights (natural [k][8]), bias, transpose h_0 ---
    for (int idx = tid; idx < 8192; idx += NTHR) {
        int jj = idx >> 10, k = idx & 1023;
        wt0[k * 8 + jj] = __ldg(&Whh0[(size_t)(jbase + jj) * 1024 + k]);
        wt1[k * 8 + jj] = __ldg(&Wih1[(size_t)(jbase + jj) * 1024 + k]);
        wt2[k * 8 + jj] = __ldg(&Whh1[(size_t)(jbase + jj) * 1024 + k]);
    }
    if (tid < 8) bias1[tid] = __ldg(&bih1[jbase + tid]) + __ldg(&bhh1[jbase + tid]);
#pragma unroll
    for (int i = 0; i < 4; i++) {              // transpose h_0 slice: 8 k x 64 b x 2 layers
        int idx = tid + i * NTHR;
        int l = idx >> 9, r = idx & 511, k = jbase + (r >> 6), b = r & 63;
        float v = __ldg(&h0in[(size_t)l * 65536 + (size_t)b * 1024 + k]);
        float* dst = l ? g_h1[1] : g_h0[1];
        __stcg(&dst[k * 64 + b], v);
    }
    gsync();   // transposed state globally visible

    u64 aA[4][4], aB[4][4];

    // --- prologue pass: H0[0] = tanh(pre[0] + Whh0·H0[-1]) ---
#pragma unroll
    for (int jp = 0; jp < 4; jp++)
#pragma unroll
        for (int bl = 0; bl < 4; bl++) aB[jp][bl] = 0ULL;
    cp_chunk(buf0, g_h0[1]);
    for (int c = 0; c < 4; c++) {
        cp_wait_all();
        __syncthreads();
        if (c < 3) cp_chunk((c & 1) ? buf0 : buf1, g_h0[1] + (size_t)(c + 1) * CK * 64);
        compute_chunk<1>((c & 1) ? buf1 : buf0, wt0 + (size_t)c * CK * 8, wt0, aB, aA, kb, b0);
    }
    __syncthreads();
    stred(r64, aB, gr, b0);
    __syncthreads();
    {
        u64 s = gather16(r64, ejp, eb);
        float lo, hi; unpack2(s, lo, hi);
        int j = jbase + ejp * 2;
        const float* pp = g_pre + (size_t)j * 64 + eb;
        __stcg(&g_h0[0][j * 64 + eb], tanhf(lo + __ldcg(pp)));
        __stcg(&g_h0[0][(j + 1) * 64 + eb], tanhf(hi + __ldcg(pp + 64)));
    }
    gsync();

    // --- main loop: interval t computes H1[t] (accA) and H0[t+1] (accB) ---
    for (int t = 0; t < TT; t++) {
        const int p = t & 1;
        const float* h0src = g_h0[p];
        const float* h1src = g_h1[p ^ 1];

#pragma unroll
        for (int jp = 0; jp < 4; jp++)
#pragma unroll
            for (int bl = 0; bl < 4; bl++) { aA[jp][bl] = 0ULL; aB[jp][bl] = 0ULL; }

        cp_chunk(buf0, h0src);
        for (int c = 0; c < 8; c++) {
            cp_wait_all();
            __syncthreads();
            if (c < 7) {
                const float* nsrc = (c + 1 < 4) ? (h0src + (size_t)(c + 1) * CK * 64)
                                                : (h1src + (size_t)(c + 1 - 4) * CK * 64);
                cp_chunk((c & 1) ? buf0 : buf1, nsrc);
            }
            const float* cbuf = (c & 1) ? buf1 : buf0;
            if (c < 4)
                compute_chunk<2>(cbuf, wt1 + (size_t)c * CK * 8, wt0 + (size_t)c * CK * 8,
                                 aA, aB, kb, b0);
            else
                compute_chunk<1>(cbuf, wt2 + (size_t)(c - 4) * CK * 8, wt2,
                                 aA, aB, kb, b0);
        }

        // epilogue A: H0[t+1] from accB (skip at t = TT-1)
        if (t < TT - 1) {
            __syncthreads();
            stred(r64, aB, gr, b0);
            __syncthreads();
            u64 s = gather16(r64, ejp, eb);
            float lo, hi; unpack2(s, lo, hi);
            int j = jbase + ejp * 2;
            const float* pp = g_pre + ((size_t)(t + 1) * 1024 + j) * 64 + eb;
            __stcg(&g_h0[p ^ 1][j * 64 + eb], tanhf(lo + __ldcg(pp)));
            __stcg(&g_h0[p ^ 1][(j + 1) * 64 + eb], tanhf(hi + __ldcg(pp + 64)));
        }

        // epilogue B: H1[t] from accA (+bias), also write outputs[t]
        __syncthreads();
        stred(r64, aA, gr, b0);
        __syncthreads();
        {
            u64 s = gather16(r64, ejp, eb);
            float lo, hi; unpack2(s, lo, hi);
            int j = jbase + ejp * 2;
            float v0 = tanhf(lo + bias1[ejp * 2]);
            float v1 = tanhf(hi + bias1[ejp * 2 + 1]);
            __stcg(&g_h1[p][j * 64 + eb], v0);
            __stcg(&g_h1[p][(j + 1) * 64 + eb], v1);
            float2 ov; ov.x = v0; ov.y = v1;
            *(float2*)&out[(size_t)t * 65536 + (size_t)eb * 1024 + j] = ov;
        }
        gsync();
    }

    // h_n: H0[511] in g_h0[1], H1[511] in g_h1[1]
    for (int e = blockIdx.x * NTHR + tid; e < 2 * BB * HH; e += NCTA * NTHR) {
        int l = e >> 16, r = e & 65535, b = r >> 10, k = r & 1023;
        const float* src = l ? g_h1[1] : g_h0[1];
        out[(size_t)TT * BB * HH + e] = __ldcg(&src[k * 64 + b]);
    }
}

// ---------------------------------------------------------------------------
extern "C" void kernel_launch(void* const* d_in, const int* in_sizes, int n_in,
                              void* d_out, int out_size)
{
    const float* input = (const float*)d_in[0];
    const float* h0in  = (const float*)d_in[1];
    const float* Wih0  = (const float*)d_in[2];
    const float* bih0  = (const float*)d_in[3];
    const float* Whh0  = (const float*)d_in[4];
    const float* bhh0  = (const float*)d_in[5];
    const float* Wih1  = (const float*)d_in[6];
    const float* bih1  = (const float*)d_in[7];
    const float* Whh1  = (const float*)d_in[8];
    const float* bhh1  = (const float*)d_in[9];
    float* out = (float*)d_out;

    const int smem_bytes = (57344 + 8) * 4;  // 229,408 B
    cudaFuncSetAttribute(rnn_persist, cudaFuncAttributeMaxDynamicSharedMemorySize, smem_bytes);

    pregemm<<<dim3(16, 256), 256>>>(input, Wih0, bih0, bhh0);
    rnn_persist<<<NCTA, NTHR, smem_bytes>>>(h0in, Whh0, Wih1, Whh1, bih1, bhh1, out);
}